// round 9
// baseline (speedup 1.0000x reference)
#include <cuda_runtime.h>
#include <math.h>

#define KK 16
#define TT 40
#define BB 16
#define NN 32
#define BN 512
#define KBN 8192
#define HH2 80
#define C1 16
#define C2 32
#define NBIN 36
#define NBLK 144
#define HWSZ (BB*NN*NBIN*48)     // 884736 per step

typedef unsigned long long ull;

__device__ float g_conv1[BB*C1*HH2*HH2];
__device__ float g_fmap [BB*HH2*HH2*C2];
__device__ float g_lhalf[KK*TT*BN*48];
__device__ int   g_cnt[KK*TT*BN];
__device__ float2 g_ent[(size_t)KK*TT*BN*32];
__device__ float g_HWhist[(size_t)TT*HWSZ];      // 141.6 MB
__device__ float g_h0 [2][BN*48];
__device__ float g_hfin[KBN*48];
__device__ float g_score[KBN];
__device__ unsigned g_bar_count;
__device__ volatile unsigned g_bar_flag;

// ---- f32x2 / fast-math helpers ----
__device__ __forceinline__ ull pk2(float lo, float hi) {
    ull r; asm("mov.b64 %0, {%1,%2};" : "=l"(r) : "f"(lo), "f"(hi)); return r;
}
__device__ __forceinline__ void upk2(ull v, float& lo, float& hi) {
    asm("mov.b64 {%0,%1}, %2;" : "=f"(lo), "=f"(hi) : "l"(v));
}
__device__ __forceinline__ void fma2(ull& a, ull x, ull y) {
    asm("fma.rn.f32x2 %0, %1, %2, %0;" : "+l"(a) : "l"(x), "l"(y));
}
__device__ __forceinline__ float sigf(float x) {
    float e; asm("ex2.approx.f32 %0, %1;" : "=f"(e) : "f"(x * -1.4426950408889634f));
    float r; asm("rcp.approx.f32 %0, %1;" : "=f"(r) : "f"(1.f + e));
    return r;
}
__device__ __forceinline__ float tanh_fast(float x) { return 2.f*sigf(2.f*x) - 1.f; }

// ---------------- conv1 ----------------
__global__ void conv1_kernel(const float* __restrict__ img,
                             const float* __restrict__ w,
                             const float* __restrict__ bias) {
    __shared__ float sW[1600];
    __shared__ float sB[16];
    for (int i = threadIdx.x; i < 1600; i += 256) sW[i] = w[i];
    if (threadIdx.x < 16) sB[threadIdx.x] = bias[threadIdx.x];
    __syncthreads();
    int idx = blockIdx.x*256 + threadIdx.x;
    int x = idx % HH2; int y = (idx/HH2) % HH2;
    int oc = (idx/(HH2*HH2)) % C1; int b = idx/(HH2*HH2*C1);
    float acc = sB[oc];
    for (int ic = 0; ic < 4; ic++)
        for (int ky = 0; ky < 5; ky++) {
            int iy = 2*y - 2 + ky;
            if (iy < 0 || iy >= 160) continue;
            const float* ip = img + ((b*4+ic)*160 + iy)*160;
            const float* wp = sW + (oc*4+ic)*25 + ky*5;
            #pragma unroll
            for (int kx = 0; kx < 5; kx++) {
                int ix = 2*x - 2 + kx;
                if (ix < 0 || ix >= 160) continue;
                acc += ip[ix] * wp[kx];
            }
        }
    g_conv1[idx] = fmaxf(acc, 0.f);
}

// ---------------- conv2: f32x2 across oc pairs ----------------
__global__ void conv2_kernel(const float* __restrict__ w2,
                             const float* __restrict__ b2) {
    __shared__ float sIn[6400];
    __shared__ __align__(16) float sW[3200];   // [(ic*25+k2)*8 + ocl]
    int blk = blockIdx.x;                       // 1600
    int ocg = blk % 4; int tile = (blk/4) % 25; int b = blk/100;
    int ty0 = (tile/5)*16, tx0 = (tile%5)*16;
    int tid = threadIdx.x;                      // 128
    for (int i = tid; i < 6400; i += 128) {
        int ic = i/400; int rem = i%400; int ly = rem/20, lx = rem%20;
        int iy = ty0 + ly - 2, ix = tx0 + lx - 2;
        sIn[i] = (iy>=0 && iy<HH2 && ix>=0 && ix<HH2)
                 ? g_conv1[((b*C1+ic)*HH2+iy)*HH2+ix] : 0.f;
    }
    for (int i = tid; i < 3200; i += 128) {
        int ic = i/200, rem = i%200, k2 = rem/8, ocl = rem%8;
        sW[i] = w2[(ocg*8+ocl)*400 + ic*25 + k2];
    }
    __syncthreads();
    int tx = tid % 16, tyh = tid / 16;
    ull a0[4], a1[4];
    #pragma unroll
    for (int o2 = 0; o2 < 4; o2++) {
        a0[o2] = pk2(b2[ocg*8+2*o2], b2[ocg*8+2*o2+1]);
        a1[o2] = a0[o2];
    }
    for (int ic = 0; ic < 16; ic++) {
        float in0[25], in1[25];
        const float* p0 = sIn + ic*400 + tyh*20 + tx;
        const float* p1 = p0 + 160;
        #pragma unroll
        for (int ky = 0; ky < 5; ky++)
            #pragma unroll
            for (int kx = 0; kx < 5; kx++) {
                in0[ky*5+kx] = p0[ky*20+kx];
                in1[ky*5+kx] = p1[ky*20+kx];
            }
        #pragma unroll
        for (int k2 = 0; k2 < 25; k2++) {
            ull i0 = pk2(in0[k2], in0[k2]);
            ull i1 = pk2(in1[k2], in1[k2]);
            const float* wb = &sW[(ic*25+k2)*8];
            #pragma unroll
            for (int o2 = 0; o2 < 4; o2++) {
                ull w = *(const ull*)(wb + 2*o2);
                fma2(a0[o2], i0, w); fma2(a1[o2], i1, w);
            }
        }
    }
    #pragma unroll
    for (int o2 = 0; o2 < 4; o2++) {
        float v0, v1, u0, u1;
        upk2(a0[o2], v0, v1); upk2(a1[o2], u0, u1);
        int oc = ocg*8 + 2*o2;
        float* d0 = &g_fmap[((b*HH2 + ty0+tyh  )*HH2 + tx0+tx)*C2 + oc];
        float* d1 = &g_fmap[((b*HH2 + ty0+tyh+8)*HH2 + tx0+tx)*C2 + oc];
        d0[0] = fmaxf(v0, 0.f); d0[1] = fmaxf(v1, 0.f);
        d1[0] = fmaxf(u0, 0.f); d1[1] = fmaxf(u1, 0.f);
    }
}

// ---------------- lhalf ----------------
__global__ void lhalf_kernel(const float* __restrict__ y_path,
                             const float* __restrict__ cur_loc,
                             const float* __restrict__ fvw,
                             const float* __restrict__ fvb) {
    int idx = blockIdx.x*256 + threadIdx.x;    // 7,864,320
    int cp = idx % 24; int row = idx / 24;
    int kt = row / BN, i2 = row % BN;
    int t = kt % TT; int b = i2 >> 5;
    float px = y_path[row*2], py = y_path[row*2+1];
    float2 out;
    if (cp < 16) {
        int u = 40 - (int)py; u = min(max(u,0), HH2-1);
        int v = (int)px;      v = min(max(v,0), HH2-1);
        out = *(const float2*)&g_fmap[((b*HH2+u)*HH2+v)*C2 + 2*cp];
    } else {
        int cc = 2*cp - 32;
        float pvx, pvy;
        if (t == 0) { pvx = cur_loc[i2*2]; pvy = cur_loc[i2*2+1]; }
        else { pvx = y_path[(row-BN)*2]; pvy = y_path[(row-BN)*2+1]; }
        float vx = (px-pvx)*10.f, vy = (py-pvy)*10.f;
        out.x = fvb[cc]   + vx*fvw[cc*2]   + vy*fvw[cc*2+1];
        out.y = fvb[cc+1] + vx*fvw[cc*2+2] + vy*fvw[cc*2+3];
    }
    *(float2*)&g_lhalf[(size_t)idx*2] = out;
}

// ---------------- bins ----------------
__device__ __forceinline__ int bin_of(float dx, float dy) {
    float dist = sqrtf(dx*dx + dy*dy);
    float dc = dist < 1e-10f ? 1e-10f : dist;
    float ct = acosf(fminf(fmaxf(dx/dc, -1.f), 1.f));
    float theta = (dy < -0.01f) ? (6.2831853071795864f - ct) : ct;
    const float R_STEP  = (float)(3.5/6.0);
    const float TH_STEP = (float)(6.283185307179586/6.0);
    int ub = (int)((dist - 0.5f)/R_STEP); ub = min(max(ub,0),5);
    int vb = (int)(theta/TH_STEP);        vb = min(max(vb,0),5);
    return ub*6 + vb;
}

__global__ void bins_kernel(const float* __restrict__ y_path) {
    __shared__ float sP[4][NN][2];
    int tid = threadIdx.x;
    int g = tid >> 5, j = tid & 31;
    int grp = blockIdx.x*4 + g;                // 10240
    int b = grp % BB; int kt = grp / BB;
    int rowbase = kt*BN + b*NN;
    sP[g][j][0] = y_path[(rowbase+j)*2];
    sP[g][j][1] = y_path[(rowbase+j)*2+1];
    __syncwarp();
    float pjx = sP[g][j][0], pjy = sP[g][j][1];
    unsigned maskbits = 0;
    #pragma unroll
    for (int n2 = 0; n2 < NN; n2++) {
        float dx = sP[g][n2][0] - pjx;
        float dy = sP[g][n2][1] - pjy;
        float dist = sqrtf(dx*dx + dy*dy);
        if (n2 != j && dist >= 0.5f && dist <= 4.0f) maskbits |= 1u << n2;
    }
    size_t rowid = rowbase + j;
    int e = 0;
    unsigned m1 = maskbits;
    while (m1) {
        int n2 = __ffs(m1) - 1; m1 &= m1 - 1;
        int bn = bin_of(sP[g][n2][0]-pjx, sP[g][n2][1]-pjy);
        int cnt = 0;
        unsigned mq = maskbits;
        while (mq) {
            int q = __ffs(mq) - 1; mq &= mq - 1;
            cnt += (bin_of(sP[g][q][0]-pjx, sP[g][q][1]-pjy) == bn);
        }
        g_ent[rowid*32 + e] = make_float2(1.f/(float)cnt,
                            __int_as_float((n2*NBIN + bn)*48));
        e++;
    }
    g_cnt[rowid] = e;
}

// ---------------- init ----------------
__global__ void init_kernel(const float* __restrict__ hx) {
    int idx = blockIdx.x*256 + threadIdx.x;    // 24576
    g_h0[0][idx] = hx[idx];
    if (idx == 0) { g_bar_count = 0u; g_bar_flag = 0u; }
}

// ---------------- grid barrier (phase 1 only) ----------------
__device__ __forceinline__ void gbar(unsigned target) {
    __syncthreads();
    if (threadIdx.x == 0) {
        __threadfence();
        unsigned old = atomicAdd(&g_bar_count, 1u);
        if (old == NBLK - 1u) {
            g_bar_count = 0u;
            __threadfence();
            g_bar_flag = target;
        } else {
            while (g_bar_flag < target) __nanosleep(32);
        }
        __threadfence();
    }
    __syncthreads();
}

// ---------------- phase 1: k=0 evolution + HW history ----------------
__global__ void __launch_bounds__(512, 1) scan1_kernel(
        const float* __restrict__ hx,   const float* __restrict__ scfw,
        const float* __restrict__ whh,  const float* __restrict__ bhh,
        const float* __restrict__ wih,  const float* __restrict__ bih,
        const float* __restrict__ scfb, const float* __restrict__ scw) {
    extern __shared__ float sm[];
    float* sWT  = sm;              // 9216
    float* sWih = sm + 9216;       // 13920 (96 x 145)
    float* sWhh = sm + 23136;      // 6960  (48 x 145)
    float* sBi  = sm + 30096;      // 144
    float* sBh  = sm + 30240;      // 144
    float* sFb  = sm + 30384;      // 48
    float* sScw = sm + 30432;      // 48
    float* sHnT = sm + 30480;      // 1584 (48 x 33)
    float* sX1  = sm + 32064;      // 384  (4 x 96)
    float* sH1  = sm + 32448;      // 192
    float* sG1  = sm + 32640;      // 576
    float* sG1n = sm + 33216;      // 192
    float2* sEnt1 = (float2*)(sm + 33408);   // 128 float2
    int*   sCnt1 = (int*)(sm + 33664);       // 4
    float* sScA1 = sm + 33668;     // 4   -> total 33672 fl

    int tid = threadIdx.x, blk = blockIdx.x;
    int bA = blk / 9, og = blk % 9;
    bool rowRole = (blk < 128);
    int r0p = blk * 4;             // k=0 rows [r0p, r0p+4)

    for (int i = tid; i < 9216; i += 512) {
        int c = i % 48, rest = i / 48, hh = rest % 48, oo = rest / 48;
        sWT[oo*2304 + hh*48 + c] = scfw[c*1728 + (og*4+oo)*48 + hh];
    }
    for (int i = tid; i < 13824; i += 512) {
        int c = i / 96, m = i % 96;
        sWih[m*145 + c] = wih[i];
    }
    for (int i = tid; i < 6912; i += 512) {
        int c = i / 48, m = i % 48;
        sWhh[m*145 + c] = whh[i];
    }
    if (tid < 144) { sBi[tid] = bih[tid]; sBh[tid] = bhh[tid]; }
    if (tid < 48)  { sFb[tid] = scfb[tid]; sScw[tid] = scw[tid]; }
    if (tid < 4)   sScA1[tid] = 0.f;
    if (rowRole && tid < 192) sH1[tid] = hx[r0p*48 + tid];
    __syncthreads();

    unsigned bar = 0;
    for (int t = 0; t < TT; t++) {
        const float* hsrc = g_h0[t & 1] + bA*1536;
        for (int i = tid; i < 1536; i += 512) {
            int n2 = i / 48, hh = i % 48;
            sHnT[hh*33 + n2] = __ldcg(hsrc + i);
        }
        if (rowRole) {
            if (tid < 192)
                sX1[(tid/48)*96 + (tid%48)] =
                    g_lhalf[(size_t)(t*BN + r0p)*48 + tid];
            if (tid < 4) {
                int cnt = g_cnt[t*BN + r0p + tid];
                sCnt1[tid] = cnt;
                for (int e = 0; e < cnt; e++)
                    sEnt1[tid*32 + e] = g_ent[(size_t)(t*BN + r0p + tid)*32 + e];
            }
        }
        __syncthreads();
        // ---- HW slice -> history ----
        float* hist = g_HWhist + (size_t)t*HWSZ;
        for (int it = tid; it < 768; it += 512) {
            int cg = it % 24, oo = (it/24) & 3, n2g = it / 96;
            float a0[4], a1[4];
            #pragma unroll
            for (int i = 0; i < 4; i++) { a0[i] = 0.f; a1[i] = 0.f; }
            const float* wt = sWT + oo*2304;
            for (int hh = 0; hh < 48; hh++) {
                float w0 = wt[hh*48 + cg], w1 = wt[hh*48 + cg + 24];
                #pragma unroll
                for (int i = 0; i < 4; i++) {
                    float hv = sHnT[hh*33 + n2g*4 + i];
                    a0[i] += hv*w0; a1[i] += hv*w1;
                }
            }
            #pragma unroll
            for (int i = 0; i < 4; i++) {
                int base = ((bA*NN + n2g*4+i)*NBIN + og*4 + oo)*48;
                hist[base + cg]      = a0[i];
                hist[base + cg + 24] = a1[i];
            }
        }
        gbar(++bar);
        if (rowRole) {
            // gather -> sX1 rhalf
            for (int it = tid; it < 192; it += 512) ;
            if (tid < 192) {
                int row = tid / 48, c = tid % 48;
                float acc = sFb[c];
                const float* hwb = hist + ((r0p + row) >> 5)*(NN*NBIN*48);
                int cnt = sCnt1[row];
                for (int e = 0; e < cnt; e++) {
                    float2 en = sEnt1[row*32 + e];
                    acc += en.x * __ldcg(hwb + __float_as_int(en.y) + c);
                }
                sX1[row*96 + 48 + c] = acc;
            }
            __syncthreads();
            // GEMM: 576 outputs
            for (int it = tid; it < 576; it += 512) {
                int row = it / 144, c = it % 144;
                int gate = c / 48, cc = c % 48;
                float acc = sBi[c] + (gate < 2 ? sBh[c] : 0.f);
                const float* xr = sX1 + row*96;
                for (int m = 0; m < 96; m++) acc += xr[m]*sWih[m*145 + c];
                const float* hr = sH1 + row*48;
                if (gate < 2) {
                    for (int m = 0; m < 48; m++) acc += hr[m]*sWhh[m*145 + c];
                } else {
                    float acc2 = sBh[96 + cc];
                    for (int m = 0; m < 48; m++) acc2 += hr[m]*sWhh[m*145 + 96 + cc];
                    sG1n[row*48 + cc] = acc2;
                }
                sG1[row*144 + c] = acc;
            }
            __syncthreads();
            // GRU + publish
            if (tid < 192) {
                int row = tid / 48, cc = tid % 48;
                float r = sigf(sG1[row*144 + cc]);
                float z = sigf(sG1[row*144 + 48 + cc]);
                float n = tanh_fast(sG1[row*144 + 96 + cc] + r*sG1n[row*48 + cc]);
                float hv = (1.f - z)*n + z*sH1[row*48 + cc];
                g_h0[1 - (t & 1)][(r0p + row)*48 + cc] = hv;
                sG1n[row*48 + cc] = hv;    // stage new h
            }
            __syncthreads();
            if (tid < 192) sH1[tid] = sG1n[tid];
            __syncthreads();
            if (tid < 4) {
                float s = 0.f;
                #pragma unroll
                for (int c = 0; c < 48; c++) s += sH1[tid*48 + c]*sScw[c];
                sScA1[tid] += s;
            }
        }
        gbar(++bar);
    }
    if (rowRole) {
        if (tid < 192) g_hfin[r0p*48 + tid] = sH1[tid];
        if (tid < 4)   g_score[r0p + tid] = sScA1[tid];
    }
}

// ---------------- phase 2: k=1..15, barrier-free ----------------
__global__ void __launch_bounds__(512, 1) scan2_kernel(
        const float* __restrict__ hx,   const float* __restrict__ whh,
        const float* __restrict__ bhh,  const float* __restrict__ wih,
        const float* __restrict__ bih,  const float* __restrict__ scfb,
        const float* __restrict__ scw) {
    extern __shared__ float sm[];
    float* sWih = sm;              // 13920
    float* sWhh = sm + 13920;      // 6960
    float* sBi  = sm + 20880;      // 144
    float* sBh  = sm + 21024;      // 144
    float* sFb  = sm + 21168;      // 48
    float* sScw = sm + 21216;      // 48
    float* sLT  = sm + 21264;      // 3168 (48 x 66)
    float* sRT  = sm + 24432;      // 3168
    float* sHT  = sm + 27600;      // 3168
    float* sNT  = sm + 30768;      // 3168
    float2* sEnt = (float2*)(sm + 33936);  // 2048 float2
    int*   sCnt = (int*)(sm + 38032);      // 64
    float* sSc  = sm + 38096;      // 1536
    float* sScA = sm + 39632;      // 64 -> total 39696 fl

    int tid = threadIdx.x, blk = blockIdx.x;   // 120 blocks
    int r0 = 512 + blk*64;
    int kq = r0 >> 9, i2b = r0 & 511;

    for (int i = tid; i < 13824; i += 512) {
        int c = i / 96, m = i % 96;
        sWih[m*145 + c] = wih[i];
    }
    for (int i = tid; i < 6912; i += 512) {
        int c = i / 48, m = i % 48;
        sWhh[m*145 + c] = whh[i];
    }
    if (tid < 144) { sBi[tid] = bih[tid]; sBh[tid] = bhh[tid]; }
    if (tid < 48)  { sFb[tid] = scfb[tid]; sScw[tid] = scw[tid]; }
    if (tid < 64)  sScA[tid] = 0.f;
    for (int i = tid; i < 3072; i += 512) {
        int row = i / 48, c = i % 48;
        sHT[c*66 + row] = hx[(i2b + row)*48 + c];
    }
    __syncthreads();

    for (int t = 0; t < TT; t++) {
        int gb = (kq*TT + t)*BN + i2b;
        for (int i = tid; i < 3072; i += 512) {
            int row = i / 48, c = i % 48;
            sLT[c*66 + row] = g_lhalf[(size_t)gb*48 + i];
        }
        if (tid < 64) {
            int cnt = g_cnt[gb + tid];
            sCnt[tid] = cnt;
            for (int e = 0; e < cnt; e++)
                sEnt[tid*32 + e] = g_ent[(size_t)(gb + tid)*32 + e];
        }
        __syncthreads();
        const float* hist = g_HWhist + (size_t)t*HWSZ;
        for (int out = tid; out < 3072; out += 512) {
            int lr = out / 48, c = out % 48;
            int cnt = sCnt[lr];
            float acc = sFb[c];
            const float* hwb = hist + ((i2b + lr) >> 5)*(NN*NBIN*48);
            for (int e = 0; e < cnt; e++) {
                float2 en = sEnt[lr*32 + e];
                acc += en.x * __ldg(hwb + __float_as_int(en.y) + c);
            }
            sRT[c*66 + lr] = acc;
        }
        __syncthreads();
        if (tid < 384) {
            int cg = tid % 24, rg = tid / 24, rl = rg*4;
            ull gr2[2][2], gz2[2][2], gnx2[2][2], gnh2[2][2];
            #pragma unroll
            for (int jj = 0; jj < 2; jj++) {
                int c = cg + 24*jj;
                ull t0;
                t0 = pk2(sBi[c]+sBh[c],       sBi[c]+sBh[c]);
                gr2[0][jj] = t0; gr2[1][jj] = t0;
                t0 = pk2(sBi[48+c]+sBh[48+c], sBi[48+c]+sBh[48+c]);
                gz2[0][jj] = t0; gz2[1][jj] = t0;
                t0 = pk2(sBi[96+c], sBi[96+c]);
                gnx2[0][jj] = t0; gnx2[1][jj] = t0;
                t0 = pk2(sBh[96+c], sBh[96+c]);
                gnh2[0][jj] = t0; gnh2[1][jj] = t0;
            }
            #define SEG(XS, WP, NACC)                                          \
            for (int m = 0; m < 48; m++) {                                     \
                ull x0 = *(const ull*)&XS[m*66 + rl];                          \
                ull x1 = *(const ull*)&XS[m*66 + rl + 2];                      \
                const float* wp = WP + m*145;                                  \
                _Pragma("unroll")                                              \
                for (int jj = 0; jj < 2; jj++) {                               \
                    int c = cg + 24*jj;                                        \
                    ull wr = pk2(wp[c], wp[c]);                                \
                    ull wz = pk2(wp[48+c], wp[48+c]);                          \
                    ull wn = pk2(wp[96+c], wp[96+c]);                          \
                    fma2(gr2[0][jj], x0, wr); fma2(gr2[1][jj], x1, wr);        \
                    fma2(gz2[0][jj], x0, wz); fma2(gz2[1][jj], x1, wz);        \
                    fma2(NACC[0][jj], x0, wn); fma2(NACC[1][jj], x1, wn);      \
                }                                                              \
            }
            SEG(sLT, sWih, gnx2)
            SEG((sRT), (sWih + 48*145), gnx2)
            SEG(sHT, sWhh, gnh2)
            #undef SEG
            float scacc[4] = {0.f, 0.f, 0.f, 0.f};
            #pragma unroll
            for (int p = 0; p < 2; p++) {
                #pragma unroll
                for (int jj = 0; jj < 2; jj++) {
                    int c = cg + 24*jj;
                    float grl, grh, gzl, gzh, gxl, gxh, ghl, ghh;
                    upk2(gr2[p][jj],  grl, grh);
                    upk2(gz2[p][jj],  gzl, gzh);
                    upk2(gnx2[p][jj], gxl, gxh);
                    upk2(gnh2[p][jj], ghl, ghh);
                    int rowl = rl + 2*p, rowh = rowl + 1;
                    float r0f = sigf(grl), z0f = sigf(gzl);
                    float n0f = tanh_fast(gxl + r0f*ghl);
                    float h0f = (1.f - z0f)*n0f + z0f*sHT[c*66 + rowl];
                    sNT[c*66 + rowl] = h0f;
                    scacc[2*p]   += h0f * sScw[c];
                    float r1f = sigf(grh), z1f = sigf(gzh);
                    float n1f = tanh_fast(gxh + r1f*ghh);
                    float h1f = (1.f - z1f)*n1f + z1f*sHT[c*66 + rowh];
                    sNT[c*66 + rowh] = h1f;
                    scacc[2*p+1] += h1f * sScw[c];
                }
            }
            #pragma unroll
            for (int i = 0; i < 4; i++) sSc[(rl+i)*24 + cg] = scacc[i];
        }
        __syncthreads();
        for (int i = tid; i < 3168; i += 512) sHT[i] = sNT[i];
        if (tid < 64) {
            float s = 0.f;
            #pragma unroll
            for (int c = 0; c < 24; c++) s += sSc[tid*24 + c];
            sScA[tid] += s;
        }
        __syncthreads();
    }
    for (int i = tid; i < 3072; i += 512) {
        int row = i / 48, c = i % 48;
        g_hfin[(size_t)r0*48 + i] = sHT[c*66 + row];
    }
    if (tid < 64) g_score[r0 + tid] = sScA[tid];
}

// ---------------- final ----------------
__global__ void final_kernel(const float* __restrict__ dyw,
                             const float* __restrict__ dyb,
                             const float* __restrict__ scb,
                             float* __restrict__ out) {
    int idx = blockIdx.x*256 + threadIdx.x;    // 663552
    if (idx < KBN*80) {
        int row = idx / 80, c = idx % 80;
        float acc = dyb[c];
        const float* hr = g_hfin + row*48;
        const float* w  = dyw + c*48;
        #pragma unroll 8
        for (int hh = 0; hh < 48; hh++) acc += hr[hh]*w[hh];
        int k = row >> 9, i2 = row & 511;
        int d = c / 40, tt = c % 40;
        out[((k*TT + tt)*BN + i2)*2 + d] = acc;
    } else {
        int row = idx - KBN*80;
        out[KBN*80 + row] = g_score[row] + 40.f*scb[0];
    }
}

// ---------------- launcher ----------------
extern "C" void kernel_launch(void* const* d_in, const int* in_sizes, int n_in,
                              void* d_out, int out_size) {
    const float* hx      = (const float*)d_in[0];
    const float* cur_loc = (const float*)d_in[1];
    const float* y_path  = (const float*)d_in[2];
    const float* image   = (const float*)d_in[3];
    const float* c1w     = (const float*)d_in[4];
    const float* c1b     = (const float*)d_in[5];
    const float* c2w     = (const float*)d_in[6];
    const float* c2b     = (const float*)d_in[7];
    const float* fvw     = (const float*)d_in[8];
    const float* fvb     = (const float*)d_in[9];
    const float* scfw    = (const float*)d_in[10];
    const float* scfb    = (const float*)d_in[11];
    const float* wih     = (const float*)d_in[12];
    const float* whh     = (const float*)d_in[13];
    const float* bih     = (const float*)d_in[14];
    const float* bhh     = (const float*)d_in[15];
    const float* dyw     = (const float*)d_in[16];
    const float* dyb     = (const float*)d_in[17];
    const float* scw     = (const float*)d_in[18];
    const float* scb     = (const float*)d_in[19];

    const int SMEM1 = 33672 * 4;   // 134688 B
    const int SMEM2 = 39696 * 4;   // 158784 B
    cudaFuncSetAttribute(scan1_kernel,
                         cudaFuncAttributeMaxDynamicSharedMemorySize, SMEM1);
    cudaFuncSetAttribute(scan2_kernel,
                         cudaFuncAttributeMaxDynamicSharedMemorySize, SMEM2);

    conv1_kernel<<<6400, 256>>>(image, c1w, c1b);
    conv2_kernel<<<1600, 128>>>(c2w, c2b);
    lhalf_kernel<<<30720,256>>>(y_path, cur_loc, fvw, fvb);
    bins_kernel <<<2560, 128>>>(y_path);
    init_kernel <<<96,   256>>>(hx);
    scan1_kernel<<<NBLK, 512, SMEM1>>>(hx, scfw, whh, bhh, wih, bih, scfb, scw);
    scan2_kernel<<<120,  512, SMEM2>>>(hx, whh, bhh, wih, bih, scfb, scw);
    final_kernel<<<2592, 256>>>(dyw, dyb, scb, (float*)d_out);
}